// round 2
// baseline (speedup 1.0000x reference)
#include <cuda_runtime.h>
#include <math.h>

#define DIMV  1024
#define HEADS 16
#define BLKSZ 129
#define DK    64
#define BSZ   4
#define NB    32
#define NTOK  (BLKSZ * NB)      // 4128
#define MROWS (BSZ * NTOK)      // 16512

// Scratch: q, k, v, o  (each [MROWS][DIMV] fp32, layout token-major, col = h*64+d)
__device__ float g_q[(size_t)MROWS * DIMV];
__device__ float g_k[(size_t)MROWS * DIMV];
__device__ float g_v[(size_t)MROWS * DIMV];
__device__ float g_o[(size_t)MROWS * DIMV];

// ---------------------------------------------------------------------------
// SGEMM:  C[M,Nn] = A[M,K] @ W[Nn,K]^T  (+ bias[Nn] if non-null)
// Classic 128x128x8 tile, 8x8 per thread, 256 threads.
// ---------------------------------------------------------------------------
#define BM 128
#define BN 128
#define BKT 8
#define TM 8
#define TN 8

__global__ __launch_bounds__(256)
void sgemm_nt(const float* __restrict__ A, const float* __restrict__ W,
              const float* __restrict__ bias, float* __restrict__ C,
              int M, int Nn, int K)
{
    __shared__ float As[BKT][BM];
    __shared__ float Ws[BKT][BN];

    const int tid  = threadIdx.x;
    const int m0   = blockIdx.y * BM;
    const int n0   = blockIdx.x * BN;

    const int lrow = tid >> 1;           // 0..127
    const int lcol = (tid & 1) * 4;      // 0 or 4
    const float* Ap = A + (size_t)(m0 + lrow) * K + lcol;
    const float* Wp = W + (size_t)(n0 + lrow) * K + lcol;

    const int trow = (tid >> 4) * TM;    // 0..120
    const int tcol = (tid & 15) * TN;    // 0..120

    float acc[TM][TN];
#pragma unroll
    for (int i = 0; i < TM; i++)
#pragma unroll
        for (int j = 0; j < TN; j++) acc[i][j] = 0.0f;

    for (int k0 = 0; k0 < K; k0 += BKT) {
        float4 a = *(const float4*)(Ap + k0);
        float4 w = *(const float4*)(Wp + k0);
        As[lcol + 0][lrow] = a.x; As[lcol + 1][lrow] = a.y;
        As[lcol + 2][lrow] = a.z; As[lcol + 3][lrow] = a.w;
        Ws[lcol + 0][lrow] = w.x; Ws[lcol + 1][lrow] = w.y;
        Ws[lcol + 2][lrow] = w.z; Ws[lcol + 3][lrow] = w.w;
        __syncthreads();

#pragma unroll
        for (int kk = 0; kk < BKT; kk++) {
            float ra[TM], rw[TN];
#pragma unroll
            for (int i = 0; i < TM; i++) ra[i] = As[kk][trow + i];
#pragma unroll
            for (int j = 0; j < TN; j++) rw[j] = Ws[kk][tcol + j];
#pragma unroll
            for (int i = 0; i < TM; i++)
#pragma unroll
                for (int j = 0; j < TN; j++)
                    acc[i][j] = fmaf(ra[i], rw[j], acc[i][j]);
        }
        __syncthreads();
    }

    float bj[TN];
#pragma unroll
    for (int j = 0; j < TN; j++) bj[j] = bias ? bias[n0 + tcol + j] : 0.0f;

#pragma unroll
    for (int i = 0; i < TM; i++) {
        float* Crow = C + (size_t)(m0 + trow + i) * Nn + n0 + tcol;
        float4 o0, o1;
        o0.x = acc[i][0] + bj[0]; o0.y = acc[i][1] + bj[1];
        o0.z = acc[i][2] + bj[2]; o0.w = acc[i][3] + bj[3];
        o1.x = acc[i][4] + bj[4]; o1.y = acc[i][5] + bj[5];
        o1.z = acc[i][6] + bj[6]; o1.w = acc[i][7] + bj[7];
        ((float4*)Crow)[0] = o0;
        ((float4*)Crow)[1] = o1;
    }
}

// ---------------------------------------------------------------------------
// Block attention: one CTA per (blk, h, b). 129x129 scores in smem (stride 133,
// conflict-free), K then V staged through the same smem region.
// ---------------------------------------------------------------------------
#define ATH 160
#define SC_LD 133
#define ATTN_SMEM ((BLKSZ * DK + BLKSZ * SC_LD) * sizeof(float))

__global__ __launch_bounds__(ATH)
void attn_block(const float* __restrict__ Q, const float* __restrict__ Kt,
                const float* __restrict__ Vt, float* __restrict__ O)
{
    extern __shared__ float sm[];
    float* Ks = sm;                 // 129*64, reused for V
    float* sc = sm + BLKSZ * DK;    // 129*133

    const int blk = blockIdx.x, h = blockIdx.y, b = blockIdx.z;
    const int tid = threadIdx.x;
    const size_t base = ((size_t)(b * NTOK + blk * BLKSZ)) * DIMV + h * DK;

    // load K tile
    for (int i = tid; i < BLKSZ * DK; i += ATH) {
        int kk = i >> 6, d = i & 63;
        Ks[i] = Kt[base + (size_t)kk * DIMV + d];
    }
    __syncthreads();

    const int q = tid;
    float4 qv[16];
    if (q < BLKSZ) {
        const float4* qp = (const float4*)(Q + base + (size_t)q * DIMV);
#pragma unroll
        for (int i = 0; i < 16; i++) qv[i] = qp[i];

        float* srow = sc + q * SC_LD;
        for (int k = 0; k < BLKSZ; k++) {
            const float4* kr = (const float4*)(Ks + k * DK);
            float s = 0.0f;
#pragma unroll
            for (int i = 0; i < 16; i++) {
                float4 kv = kr[i];
                s = fmaf(qv[i].x, kv.x, s); s = fmaf(qv[i].y, kv.y, s);
                s = fmaf(qv[i].z, kv.z, s); s = fmaf(qv[i].w, kv.w, s);
            }
            srow[k] = s * 0.125f;   // 1/sqrt(64)
        }
    }
    __syncthreads();   // everyone done reading Ks

    // overwrite Ks with V tile
    for (int i = tid; i < BLKSZ * DK; i += ATH) {
        int kk = i >> 6, d = i & 63;
        Ks[i] = Vt[base + (size_t)kk * DIMV + d];
    }

    // per-row softmax (only touches own sc row)
    float inv = 0.0f;
    if (q < BLKSZ) {
        float* srow = sc + q * SC_LD;
        float m = -1e30f;
        for (int k = 0; k < BLKSZ; k++) m = fmaxf(m, srow[k]);
        float sum = 0.0f;
        for (int k = 0; k < BLKSZ; k++) {
            float e = __expf(srow[k] - m);
            srow[k] = e;
            sum += e;
        }
        inv = 1.0f / sum;
    }
    __syncthreads();   // V loaded

    if (q < BLKSZ) {
        float4 accv[16];
#pragma unroll
        for (int i = 0; i < 16; i++) accv[i] = make_float4(0.f, 0.f, 0.f, 0.f);
        float* srow = sc + q * SC_LD;
        for (int k = 0; k < BLKSZ; k++) {
            float p = srow[k];
            const float4* vr = (const float4*)(Ks + k * DK);
#pragma unroll
            for (int i = 0; i < 16; i++) {
                float4 vv = vr[i];
                accv[i].x = fmaf(p, vv.x, accv[i].x);
                accv[i].y = fmaf(p, vv.y, accv[i].y);
                accv[i].z = fmaf(p, vv.z, accv[i].z);
                accv[i].w = fmaf(p, vv.w, accv[i].w);
            }
        }
        float4* op = (float4*)(O + base + (size_t)q * DIMV);
#pragma unroll
        for (int i = 0; i < 16; i++) {
            float4 r;
            r.x = accv[i].x * inv; r.y = accv[i].y * inv;
            r.z = accv[i].z * inv; r.w = accv[i].w * inv;
            op[i] = r;
        }
    }
}

// ---------------------------------------------------------------------------
// Global attention over the 32 block-start tokens per (b,h); adds into O.
// Must run after attn_block (same stream ordering).
// ---------------------------------------------------------------------------
__global__ __launch_bounds__(32)
void attn_global(const float* __restrict__ Q, const float* __restrict__ Kt,
                 const float* __restrict__ Vt, float* __restrict__ O)
{
    __shared__ float Kg[NB * DK];
    __shared__ float Vg[NB * DK];
    const int h = blockIdx.x, b = blockIdx.y;
    const int tid = threadIdx.x;

    for (int i = tid; i < NB * DK; i += 32) {
        int j = i >> 6, d = i & 63;
        size_t r = ((size_t)(b * NTOK + j * BLKSZ)) * DIMV + h * DK + d;
        Kg[i] = Kt[r];
        Vg[i] = Vt[r];
    }
    __syncthreads();

    const int qj = tid;   // 0..31
    const size_t qbase = ((size_t)(b * NTOK + qj * BLKSZ)) * DIMV + h * DK;

    float qv[DK];
#pragma unroll
    for (int d = 0; d < DK; d++) qv[d] = Q[qbase + d];

    float s[NB];
    float m = -1e30f;
#pragma unroll
    for (int k = 0; k < NB; k++) {
        float dot = 0.0f;
#pragma unroll
        for (int d = 0; d < DK; d++) dot = fmaf(qv[d], Kg[k * DK + d], dot);
        s[k] = dot * 0.125f;
        m = fmaxf(m, s[k]);
    }
    float sum = 0.0f;
#pragma unroll
    for (int k = 0; k < NB; k++) { s[k] = __expf(s[k] - m); sum += s[k]; }
    float inv = 1.0f / sum;

    float acc[DK];
#pragma unroll
    for (int d = 0; d < DK; d++) acc[d] = 0.0f;
#pragma unroll
    for (int k = 0; k < NB; k++) {
        float p = s[k];
#pragma unroll
        for (int d = 0; d < DK; d++) acc[d] = fmaf(p, Vg[k * DK + d], acc[d]);
    }
#pragma unroll
    for (int d = 0; d < DK; d++) O[qbase + d] += acc[d] * inv;
}

// ---------------------------------------------------------------------------
extern "C" void kernel_launch(void* const* d_in, const int* in_sizes, int n_in,
                              void* d_out, int out_size)
{
    const float* x  = (const float*)d_in[0];
    const float* Wq = (const float*)d_in[1];
    const float* Wk = (const float*)d_in[2];
    const float* Wv = (const float*)d_in[3];
    const float* Wo = (const float*)d_in[4];
    const float* bo = (const float*)d_in[5];
    float* out = (float*)d_out;

    float *q, *k, *v, *o;
    cudaGetSymbolAddress((void**)&q, g_q);
    cudaGetSymbolAddress((void**)&k, g_k);
    cudaGetSymbolAddress((void**)&v, g_v);
    cudaGetSymbolAddress((void**)&o, g_o);

    cudaFuncSetAttribute(attn_block, cudaFuncAttributeMaxDynamicSharedMemorySize,
                         (int)ATTN_SMEM);

    dim3 ggrid(DIMV / BN, MROWS / BM);   // (8, 129)

    sgemm_nt<<<ggrid, 256>>>(x, Wq, nullptr, q, MROWS, DIMV, DIMV);
    sgemm_nt<<<ggrid, 256>>>(x, Wk, nullptr, k, MROWS, DIMV, DIMV);
    sgemm_nt<<<ggrid, 256>>>(x, Wv, nullptr, v, MROWS, DIMV, DIMV);

    attn_block<<<dim3(NB, HEADS, BSZ), ATH, ATTN_SMEM>>>(q, k, v, o);
    attn_global<<<dim3(HEADS, BSZ), 32>>>(q, k, v, o);

    sgemm_nt<<<ggrid, 256>>>(o, Wo, bo, out, MROWS, DIMV, DIMV);
}

// round 4
// speedup vs baseline: 2.3907x; 2.3907x over previous
#include <cuda_runtime.h>
#include <cuda_bf16.h>
#include <math.h>
#include <stdint.h>

#define DIMV  1024
#define HEADS 16
#define BLKSZ 129
#define DK    64
#define BSZ   4
#define NB    32
#define NTOK  (BLKSZ * NB)      // 4128
#define MROWS (BSZ * NTOK)      // 16512

// fp32 scratch
__device__ float g_q[(size_t)MROWS * DIMV];
__device__ float g_k[(size_t)MROWS * DIMV];
__device__ float g_v[(size_t)MROWS * DIMV];
__device__ float g_o[(size_t)MROWS * DIMV];
// bf16 split scratch
__device__ __nv_bfloat16 g_ah[(size_t)MROWS * DIMV];
__device__ __nv_bfloat16 g_al[(size_t)MROWS * DIMV];
__device__ __nv_bfloat16 g_wh[(size_t)DIMV * DIMV];
__device__ __nv_bfloat16 g_wl[(size_t)DIMV * DIMV];

// ---------------------------------------------------------------------------
// PTX helpers (all legal on compute_103 base target)
// ---------------------------------------------------------------------------
__device__ __forceinline__ uint32_t smem_u32(const void* p) {
    uint32_t a;
    asm("{ .reg .u64 t; cvta.to.shared.u64 t, %1; cvt.u32.u64 %0, t; }"
        : "=r"(a) : "l"(p));
    return a;
}
#define CP_ASYNC16(dst, src) \
    asm volatile("cp.async.cg.shared.global [%0], [%1], 16;" :: "r"(dst), "l"(src))
#define CP_COMMIT() asm volatile("cp.async.commit_group;")
#define CP_WAIT(n)  asm volatile("cp.async.wait_group %0;" :: "n"(n))

#define LDSM_X4(r0, r1, r2, r3, addr) \
    asm volatile("ldmatrix.sync.aligned.m8n8.x4.shared.b16 {%0,%1,%2,%3}, [%4];" \
        : "=r"(r0), "=r"(r1), "=r"(r2), "=r"(r3) : "r"(addr))

#define MMA16816(d, a, b) \
    asm volatile("mma.sync.aligned.m16n8k16.row.col.f32.bf16.bf16.f32 " \
        "{%0,%1,%2,%3}, {%4,%5,%6,%7}, {%8,%9}, {%0,%1,%2,%3};" \
        : "+f"((d)[0]), "+f"((d)[1]), "+f"((d)[2]), "+f"((d)[3]) \
        : "r"((a)[0]), "r"((a)[1]), "r"((a)[2]), "r"((a)[3]), \
          "r"((b)[0]), "r"((b)[1]))

// ---------------------------------------------------------------------------
// HMMA split-bf16 GEMM:  C[M,Nn] = A @ W^T (+bias), fp32 out
// A given as Ah/Al [M,1024] bf16, W as Wh/Wl [Nn,1024] bf16 (K-major rows).
// CTA tile 128x128x32, 8 warps (2x4 -> 64x32 warp tile), double buffer.
// ---------------------------------------------------------------------------
#define GK     1024
#define BKG    32
#define NKI    (GK / BKG)        // 32
#define TILE_B 8192              // 128 rows * 64B
#define SMEM_G (2 * 4 * TILE_B)  // 65536

// 64-byte rows, 4x16B chunks, XOR swizzle (conflict-free for ldmatrix phases)
__device__ __forceinline__ uint32_t sw_off(int row, int c) {
    int q = c ^ (row & 3) ^ ((row >> 2) & 1);
    return (uint32_t)(row * 64 + q * 16);
}

__device__ __forceinline__ void g_load_stage(
    uint32_t smem_base, int s, int k0, int m0, int n0, int tid,
    const __nv_bfloat16* __restrict__ Ah, const __nv_bfloat16* __restrict__ Al,
    const __nv_bfloat16* __restrict__ Bh, const __nv_bfloat16* __restrict__ Bl)
{
#pragma unroll
    for (int t = 0; t < 4; t++) {
        const __nv_bfloat16* base = (t == 0) ? Ah : (t == 1) ? Al : (t == 2) ? Bh : Bl;
        const int r0 = (t < 2) ? m0 : n0;
        const uint32_t tbase = smem_base + (uint32_t)(s * 4 + t) * TILE_B;
#pragma unroll
        for (int j = 0; j < 2; j++) {
            int idx = tid + j * 256;        // 512 chunks per tile
            int row = idx >> 2, c = idx & 3;
            const void* src = base + (size_t)(r0 + row) * GK + k0 + c * 8;
            CP_ASYNC16(tbase + sw_off(row, c), src);
        }
    }
}

__global__ __launch_bounds__(256, 1)
void gemm_mma(const __nv_bfloat16* __restrict__ Ah, const __nv_bfloat16* __restrict__ Al,
              const __nv_bfloat16* __restrict__ Bh, const __nv_bfloat16* __restrict__ Bl,
              const float* __restrict__ bias, float* __restrict__ C, int Nn)
{
    extern __shared__ char smem[];
    const uint32_t smem_base = smem_u32(smem);
    const int tid = threadIdx.x;
    const int wid = tid >> 5, lid = tid & 31;
    const int warp_m = wid >> 2, warp_n = wid & 3;   // 2 x 4
    const int m0 = blockIdx.y * 128, n0 = blockIdx.x * 128;

    float acc[4][4][4];
#pragma unroll
    for (int i = 0; i < 4; i++)
#pragma unroll
        for (int j = 0; j < 4; j++)
#pragma unroll
            for (int f = 0; f < 4; f++) acc[i][j][f] = 0.0f;

    g_load_stage(smem_base, 0, 0,   m0, n0, tid, Ah, Al, Bh, Bl); CP_COMMIT();
    g_load_stage(smem_base, 1, BKG, m0, n0, tid, Ah, Al, Bh, Bl); CP_COMMIT();

    // ldmatrix lane addressing (constant per thread, per tile type)
    const int a_row = (lid & 15);                 // + i*16 + warp_m*64
    const int a_chk = (lid >> 4) & 1;             // + kk/8
    const int b_row = (lid & 7) + (((lid >> 4) & 1) << 3);  // + j2*16 + warp_n*32
    const int b_chk = (lid >> 3) & 1;             // + kk/8

    for (int ks = 0; ks < NKI; ks++) {
        if (ks + 1 < NKI) { CP_WAIT(1); } else { CP_WAIT(0); }
        __syncthreads();

        const int buf = ks & 1;
        const uint32_t bAh = smem_base + (uint32_t)(buf * 4 + 0) * TILE_B;
        const uint32_t bAl = smem_base + (uint32_t)(buf * 4 + 1) * TILE_B;
        const uint32_t bBh = smem_base + (uint32_t)(buf * 4 + 2) * TILE_B;
        const uint32_t bBl = smem_base + (uint32_t)(buf * 4 + 3) * TILE_B;

#pragma unroll
        for (int kk = 0; kk < BKG; kk += 16) {
            uint32_t ah[4][4], al[4][4], bh[4][2], bl[4][2];
            const int kc = kk >> 3;
#pragma unroll
            for (int i = 0; i < 4; i++) {
                int r = warp_m * 64 + i * 16 + a_row;
                uint32_t off = sw_off(r, kc + a_chk);
                LDSM_X4(ah[i][0], ah[i][1], ah[i][2], ah[i][3], bAh + off);
                LDSM_X4(al[i][0], al[i][1], al[i][2], al[i][3], bAl + off);
            }
#pragma unroll
            for (int j2 = 0; j2 < 2; j2++) {
                int r = warp_n * 32 + j2 * 16 + b_row;
                uint32_t off = sw_off(r, kc + b_chk);
                LDSM_X4(bh[j2 * 2][0], bh[j2 * 2][1], bh[j2 * 2 + 1][0], bh[j2 * 2 + 1][1],
                        bBh + off);
                LDSM_X4(bl[j2 * 2][0], bl[j2 * 2][1], bl[j2 * 2 + 1][0], bl[j2 * 2 + 1][1],
                        bBl + off);
            }
#pragma unroll
            for (int i = 0; i < 4; i++)
#pragma unroll
                for (int j = 0; j < 4; j++) {
                    MMA16816(acc[i][j], ah[i], bh[j]);
                    MMA16816(acc[i][j], ah[i], bl[j]);
                    MMA16816(acc[i][j], al[i], bh[j]);
                }
        }
        __syncthreads();
        if (ks + 2 < NKI) {
            g_load_stage(smem_base, buf, (ks + 2) * BKG, m0, n0, tid, Ah, Al, Bh, Bl);
            CP_COMMIT();
        }
    }

    // epilogue
    const int g = lid >> 2, t = lid & 3;
#pragma unroll
    for (int i = 0; i < 4; i++) {
#pragma unroll
        for (int j = 0; j < 4; j++) {
            int row0 = m0 + warp_m * 64 + i * 16 + g;
            int col  = n0 + warp_n * 32 + j * 8 + 2 * t;
            float b0 = 0.f, b1 = 0.f;
            if (bias) { b0 = bias[col]; b1 = bias[col + 1]; }
            float2 v0 = make_float2(acc[i][j][0] + b0, acc[i][j][1] + b1);
            float2 v1 = make_float2(acc[i][j][2] + b0, acc[i][j][3] + b1);
            *(float2*)(C + (size_t)row0 * Nn + col)       = v0;
            *(float2*)(C + (size_t)(row0 + 8) * Nn + col) = v1;
        }
    }
}

// ---------------------------------------------------------------------------
// fp32 -> bf16 hi/lo split
// ---------------------------------------------------------------------------
__global__ __launch_bounds__(256)
void split_bf16(const float4* __restrict__ in, __nv_bfloat162* __restrict__ hi,
                __nv_bfloat162* __restrict__ lo, int n4)
{
    int i = blockIdx.x * 256 + threadIdx.x;
    if (i >= n4) return;
    float4 v = in[i];
    __nv_bfloat16 h0 = __float2bfloat16_rn(v.x), h1 = __float2bfloat16_rn(v.y);
    __nv_bfloat16 h2 = __float2bfloat16_rn(v.z), h3 = __float2bfloat16_rn(v.w);
    __nv_bfloat16 l0 = __float2bfloat16_rn(v.x - __bfloat162float(h0));
    __nv_bfloat16 l1 = __float2bfloat16_rn(v.y - __bfloat162float(h1));
    __nv_bfloat16 l2 = __float2bfloat16_rn(v.z - __bfloat162float(h2));
    __nv_bfloat16 l3 = __float2bfloat16_rn(v.w - __bfloat162float(h3));
    hi[2 * i]     = __nv_bfloat162(h0, h1);
    hi[2 * i + 1] = __nv_bfloat162(h2, h3);
    lo[2 * i]     = __nv_bfloat162(l0, l1);
    lo[2 * i + 1] = __nv_bfloat162(l2, l3);
}

// ---------------------------------------------------------------------------
// Block attention (unchanged from passing R1 kernel)
// ---------------------------------------------------------------------------
#define ATH 160
#define SC_LD 133
#define ATTN_SMEM ((BLKSZ * DK + BLKSZ * SC_LD) * sizeof(float))

__global__ __launch_bounds__(ATH)
void attn_block(const float* __restrict__ Q, const float* __restrict__ Kt,
                const float* __restrict__ Vt, float* __restrict__ O)
{
    extern __shared__ float sm[];
    float* Ks = sm;
    float* sc = sm + BLKSZ * DK;

    const int blk = blockIdx.x, h = blockIdx.y, b = blockIdx.z;
    const int tid = threadIdx.x;
    const size_t base = ((size_t)(b * NTOK + blk * BLKSZ)) * DIMV + h * DK;

    for (int i = tid; i < BLKSZ * DK; i += ATH) {
        int kk = i >> 6, d = i & 63;
        Ks[i] = Kt[base + (size_t)kk * DIMV + d];
    }
    __syncthreads();

    const int q = tid;
    float4 qv[16];
    if (q < BLKSZ) {
        const float4* qp = (const float4*)(Q + base + (size_t)q * DIMV);
#pragma unroll
        for (int i = 0; i < 16; i++) qv[i] = qp[i];
        float* srow = sc + q * SC_LD;
        for (int k = 0; k < BLKSZ; k++) {
            const float4* kr = (const float4*)(Ks + k * DK);
            float s = 0.0f;
#pragma unroll
            for (int i = 0; i < 16; i++) {
                float4 kv = kr[i];
                s = fmaf(qv[i].x, kv.x, s); s = fmaf(qv[i].y, kv.y, s);
                s = fmaf(qv[i].z, kv.z, s); s = fmaf(qv[i].w, kv.w, s);
            }
            srow[k] = s * 0.125f;
        }
    }
    __syncthreads();

    for (int i = tid; i < BLKSZ * DK; i += ATH) {
        int kk = i >> 6, d = i & 63;
        Ks[i] = Vt[base + (size_t)kk * DIMV + d];
    }

    float inv = 0.0f;
    if (q < BLKSZ) {
        float* srow = sc + q * SC_LD;
        float m = -1e30f;
        for (int k = 0; k < BLKSZ; k++) m = fmaxf(m, srow[k]);
        float sum = 0.0f;
        for (int k = 0; k < BLKSZ; k++) {
            float e = __expf(srow[k] - m);
            srow[k] = e;
            sum += e;
        }
        inv = 1.0f / sum;
    }
    __syncthreads();

    if (q < BLKSZ) {
        float4 accv[16];
#pragma unroll
        for (int i = 0; i < 16; i++) accv[i] = make_float4(0.f, 0.f, 0.f, 0.f);
        float* srow = sc + q * SC_LD;
        for (int k = 0; k < BLKSZ; k++) {
            float p = srow[k];
            const float4* vr = (const float4*)(Ks + k * DK);
#pragma unroll
            for (int i = 0; i < 16; i++) {
                float4 vv = vr[i];
                accv[i].x = fmaf(p, vv.x, accv[i].x);
                accv[i].y = fmaf(p, vv.y, accv[i].y);
                accv[i].z = fmaf(p, vv.z, accv[i].z);
                accv[i].w = fmaf(p, vv.w, accv[i].w);
            }
        }
        float4* op = (float4*)(O + base + (size_t)q * DIMV);
#pragma unroll
        for (int i = 0; i < 16; i++) {
            float4 r;
            r.x = accv[i].x * inv; r.y = accv[i].y * inv;
            r.z = accv[i].z * inv; r.w = accv[i].w * inv;
            op[i] = r;
        }
    }
}

__global__ __launch_bounds__(32)
void attn_global(const float* __restrict__ Q, const float* __restrict__ Kt,
                 const float* __restrict__ Vt, float* __restrict__ O)
{
    __shared__ float Kg[NB * DK];
    __shared__ float Vg[NB * DK];
    const int h = blockIdx.x, b = blockIdx.y;
    const int tid = threadIdx.x;

    for (int i = tid; i < NB * DK; i += 32) {
        int j = i >> 6, d = i & 63;
        size_t r = ((size_t)(b * NTOK + j * BLKSZ)) * DIMV + h * DK + d;
        Kg[i] = Kt[r];
        Vg[i] = Vt[r];
    }
    __syncthreads();

    const int qj = tid;
    const size_t qbase = ((size_t)(b * NTOK + qj * BLKSZ)) * DIMV + h * DK;

    float qv[DK];
#pragma unroll
    for (int d = 0; d < DK; d++) qv[d] = Q[qbase + d];

    float s[NB];
    float m = -1e30f;
#pragma unroll
    for (int k = 0; k < NB; k++) {
        float dot = 0.0f;
#pragma unroll
        for (int d = 0; d < DK; d++) dot = fmaf(qv[d], Kg[k * DK + d], dot);
        s[k] = dot * 0.125f;
        m = fmaxf(m, s[k]);
    }
    float sum = 0.0f;
#pragma unroll
    for (int k = 0; k < NB; k++) { s[k] = __expf(s[k] - m); sum += s[k]; }
    float inv = 1.0f / sum;

    float acc[DK];
#pragma unroll
    for (int d = 0; d < DK; d++) acc[d] = 0.0f;
#pragma unroll
    for (int k = 0; k < NB; k++) {
        float p = s[k];
#pragma unroll
        for (int d = 0; d < DK; d++) acc[d] = fmaf(p, Vg[k * DK + d], acc[d]);
    }
#pragma unroll
    for (int d = 0; d < DK; d++) O[qbase + d] += acc[d] * inv;
}

// ---------------------------------------------------------------------------
extern "C" void kernel_launch(void* const* d_in, const int* in_sizes, int n_in,
                              void* d_out, int out_size)
{
    const float* x  = (const float*)d_in[0];
    const float* Wq = (const float*)d_in[1];
    const float* Wk = (const float*)d_in[2];
    const float* Wv = (const float*)d_in[3];
    const float* Wo = (const float*)d_in[4];
    const float* bo = (const float*)d_in[5];
    float* out = (float*)d_out;

    float *q, *k, *v, *o;
    __nv_bfloat16 *ah, *al, *wh, *wl;
    cudaGetSymbolAddress((void**)&q, g_q);
    cudaGetSymbolAddress((void**)&k, g_k);
    cudaGetSymbolAddress((void**)&v, g_v);
    cudaGetSymbolAddress((void**)&o, g_o);
    cudaGetSymbolAddress((void**)&ah, g_ah);
    cudaGetSymbolAddress((void**)&al, g_al);
    cudaGetSymbolAddress((void**)&wh, g_wh);
    cudaGetSymbolAddress((void**)&wl, g_wl);

    cudaFuncSetAttribute(attn_block, cudaFuncAttributeMaxDynamicSharedMemorySize,
                         (int)ATTN_SMEM);
    cudaFuncSetAttribute(gemm_mma, cudaFuncAttributeMaxDynamicSharedMemorySize,
                         SMEM_G);

    const int nX4 = MROWS * DIMV / 4;
    const int nW4 = DIMV * DIMV / 4;
    dim3 ggrid(DIMV / 128, MROWS / 128);   // (8, 129)

    split_bf16<<<(nX4 + 255) / 256, 256>>>((const float4*)x,
        (__nv_bfloat162*)ah, (__nv_bfloat162*)al, nX4);

    split_bf16<<<(nW4 + 255) / 256, 256>>>((const float4*)Wq,
        (__nv_bfloat162*)wh, (__nv_bfloat162*)wl, nW4);
    gemm_mma<<<ggrid, 256, SMEM_G>>>(ah, al, wh, wl, nullptr, q, DIMV);

    split_bf16<<<(nW4 + 255) / 256, 256>>>((const float4*)Wk,
        (__nv_bfloat162*)wh, (__nv_bfloat162*)wl, nW4);
    gemm_mma<<<ggrid, 256, SMEM_G>>>(ah, al, wh, wl, nullptr, k, DIMV);

    split_bf16<<<(nW4 + 255) / 256, 256>>>((const float4*)Wv,
        (__nv_bfloat162*)wh, (__nv_bfloat162*)wl, nW4);
    gemm_mma<<<ggrid, 256, SMEM_G>>>(ah, al, wh, wl, nullptr, v, DIMV);

    attn_block<<<dim3(NB, HEADS, BSZ), ATH, ATTN_SMEM>>>(q, k, v, o);
    attn_global<<<dim3(HEADS, BSZ), 32>>>(q, k, v, o);

    split_bf16<<<(nX4 + 255) / 256, 256>>>((const float4*)o,
        (__nv_bfloat162*)ah, (__nv_bfloat162*)al, nX4);
    split_bf16<<<(nW4 + 255) / 256, 256>>>((const float4*)Wo,
        (__nv_bfloat162*)wh, (__nv_bfloat162*)wl, nW4);
    gemm_mma<<<ggrid, 256, SMEM_G>>>(ah, al, wh, wl, bo, out, DIMV);
}